// round 13
// baseline (speedup 1.0000x reference)
#include <cuda_runtime.h>
#include <cstdint>

#define NDIM 16
#define MAXN 50048

__device__ float g_deg[MAXN];

// ---------- packed f32x2 helpers ----------
__device__ __forceinline__ void ffma2(uint64_t &acc, uint64_t a, uint64_t b) {
    asm("fma.rn.f32x2 %0, %1, %2, %0;" : "+l"(acc) : "l"(a), "l"(b));
}
__device__ __forceinline__ uint64_t pack2(float lo, float hi) {
    uint64_t r; asm("mov.b64 %0, {%1, %2};" : "=l"(r) : "f"(lo), "f"(hi)); return r;
}
__device__ __forceinline__ void unpack2(uint64_t v, float &lo, float &hi) {
    asm("mov.b64 {%0, %1}, %2;" : "=f"(lo), "=f"(hi) : "l"(v));
}
__device__ __forceinline__ void red_add_v4(float* p, float a, float b, float c, float d) {
    asm volatile("red.global.add.v4.f32 [%0], {%1, %2, %3, %4};"
                 :: "l"(p), "f"(a), "f"(b), "f"(c), "f"(d) : "memory");
}

// ---------- small utility kernels ----------
__global__ void init_kernel(const float* __restrict__ x, float* __restrict__ out, int n) {
    int i = blockIdx.x * blockDim.x + threadIdx.x;
    int nd = n * NDIM;
    if (i < nd) out[i] = x[i];
    if (i < n) g_deg[i] = 0.f;
}

__global__ void deg_kernel(const int* __restrict__ ei, int E, int n) {
    int e = blockIdx.x * blockDim.x + threadIdx.x;
    if (e >= E) return;
    int s = ei[e], d = ei[E + e];
    if ((unsigned)s < (unsigned)n) atomicAdd(&g_deg[s], 1.f);
    if ((unsigned)d < (unsigned)n) atomicAdd(&g_deg[d], 1.f);
}

__global__ void relu_kernel(float* __restrict__ out, int nd) {
    int i = blockIdx.x * blockDim.x + threadIdx.x;
    if (i < nd) out[i] = fmaxf(out[i], 0.f);
}

// ---------- main edge kernel: one edge/thread, f32x2 MLP, scalar v-accum, red.v4 ----------
__global__ void __launch_bounds__(128, 4)
edge_kernel(const float* __restrict__ x, const int* __restrict__ ei,
            const float* __restrict__ W1, const float* __restrict__ b1,
            const float* __restrict__ W2, const float* __restrict__ b2,
            float* __restrict__ out, int E, int n)
{
    // sW1[k][j] = W1[j][k]  (transposed: j contiguous -> LDS.128 gives packed (j,j+1) pairs)
    __shared__ __align__(16) float sW1[32 * 64];
    // sW2[i][j] = W2[i][j]
    __shared__ __align__(16) float sW2[16 * 64];
    __shared__ float sb1[64];
    __shared__ float sb2[16];

    for (int idx = threadIdx.x; idx < 64 * 32; idx += blockDim.x) {
        int j = idx >> 5, k = idx & 31;
        sW1[k * 64 + j] = W1[idx];
    }
    for (int idx = threadIdx.x; idx < 16 * 64; idx += blockDim.x) sW2[idx] = W2[idx];
    if (threadIdx.x < 64) sb1[threadIdx.x] = b1[threadIdx.x];
    if (threadIdx.x < 16) sb2[threadIdx.x] = b2[threadIdx.x];
    __syncthreads();

    int e = blockIdx.x * blockDim.x + threadIdx.x;
    if (e >= E) return;
    int s = ei[e];
    int d = ei[E + e];
    if ((unsigned)s >= (unsigned)n || (unsigned)d >= (unsigned)n) return;

    // in[0..15] = x[src], in[16..31] = x[dst]
    float in[32];
    {
        const float4* ps = (const float4*)(x + (size_t)s * NDIM);
        const float4* pd = (const float4*)(x + (size_t)d * NDIM);
        #pragma unroll
        for (int q = 0; q < 4; q++) {
            float4 a = ps[q];
            in[4 * q + 0] = a.x; in[4 * q + 1] = a.y;
            in[4 * q + 2] = a.z; in[4 * q + 3] = a.w;
        }
        #pragma unroll
        for (int q = 0; q < 4; q++) {
            float4 a = pd[q];
            in[16 + 4 * q + 0] = a.x; in[16 + 4 * q + 1] = a.y;
            in[16 + 4 * q + 2] = a.z; in[16 + 4 * q + 3] = a.w;
        }
    }

    // Scalar accumulators for MLP outputs (saves 32 regs vs packed pairs).
    float v0[16], v1[16];
    #pragma unroll
    for (int i = 0; i < 16; i++) { v0[i] = 0.f; v1[i] = 0.f; }

    #pragma unroll 1
    for (int jj = 0; jj < 64; jj += 8) {
        // hp[dir][p] = packed (h_{jj+2p}, h_{jj+2p+1})
        uint64_t hp0[4], hp1[4];
        #pragma unroll
        for (int p = 0; p < 4; p++) {
            uint64_t b = pack2(sb1[jj + 2 * p], sb1[jj + 2 * p + 1]);
            hp0[p] = b; hp1[p] = b;
        }
        #pragma unroll
        for (int k = 0; k < 32; k++) {
            ulonglong2 wa = *(const ulonglong2*)(sW1 + k * 64 + jj);      // pairs (j0,j1),(j2,j3)
            ulonglong2 wb = *(const ulonglong2*)(sW1 + k * 64 + jj + 4);  // pairs (j4,j5),(j6,j7)
            uint64_t A0 = pack2(in[k], in[k]);
            uint64_t A1 = pack2(in[k ^ 16], in[k ^ 16]);
            ffma2(hp0[0], wa.x, A0); ffma2(hp1[0], wa.x, A1);
            ffma2(hp0[1], wa.y, A0); ffma2(hp1[1], wa.y, A1);
            ffma2(hp0[2], wb.x, A0); ffma2(hp1[2], wb.x, A1);
            ffma2(hp0[3], wb.y, A0); ffma2(hp1[3], wb.y, A1);
        }
        // ReLU on packed pairs
        #pragma unroll
        for (int p = 0; p < 4; p++) {
            float l, h;
            unpack2(hp0[p], l, h);
            hp0[p] = pack2(fmaxf(l, 0.f), fmaxf(h, 0.f));
            unpack2(hp1[p], l, h);
            hp1[p] = pack2(fmaxf(l, 0.f), fmaxf(h, 0.f));
        }
        // W2 pass: short packed temps folded into scalar accumulators
        #pragma unroll
        for (int i = 0; i < 16; i++) {
            ulonglong2 wa = *(const ulonglong2*)(sW2 + i * 64 + jj);
            ulonglong2 wb = *(const ulonglong2*)(sW2 + i * 64 + jj + 4);
            uint64_t t0 = 0ull, t1 = 0ull;
            ffma2(t0, wa.x, hp0[0]); ffma2(t0, wa.y, hp0[1]);
            ffma2(t0, wb.x, hp0[2]); ffma2(t0, wb.y, hp0[3]);
            ffma2(t1, wa.x, hp1[0]); ffma2(t1, wa.y, hp1[1]);
            ffma2(t1, wb.x, hp1[2]); ffma2(t1, wb.y, hp1[3]);
            float l, h;
            unpack2(t0, l, h); v0[i] += l + h;
            unpack2(t1, l, h); v1[i] += l + h;
        }
    }

    // add bias, normalize
    float n0 = 0.f, n1 = 0.f;
    #pragma unroll
    for (int i = 0; i < 16; i++) {
        v0[i] += sb2[i]; v1[i] += sb2[i];
        n0 += v0[i] * v0[i];
        n1 += v1[i] * v1[i];
    }
    float inv0 = 1.f / fmaxf(sqrtf(n0), 1e-12f);
    float inv1 = 1.f / fmaxf(sqrtf(n1), 1e-12f);
    #pragma unroll
    for (int i = 0; i < 16; i++) { v0[i] *= inv0; v1[i] *= inv1; }
    // v0 = Householder vec of F_s, v1 = of F_d

    float coef = rsqrtf(fmaxf(g_deg[s], 1e-5f)) * rsqrtf(fmaxf(g_deg[d], 1e-5f));

    // message to src: += coef * F_s(F_d x_d);  F u y = y - 2(u.y)u
    {
        float tv[16];
        float dd = 0.f;
        #pragma unroll
        for (int i = 0; i < 16; i++) dd += v1[i] * in[16 + i];
        dd *= 2.f;
        #pragma unroll
        for (int i = 0; i < 16; i++) tv[i] = in[16 + i] - dd * v1[i];
        float ds = 0.f;
        #pragma unroll
        for (int i = 0; i < 16; i++) ds += v0[i] * tv[i];
        ds *= 2.f;
        float* po = out + (size_t)s * NDIM;
        #pragma unroll
        for (int q = 0; q < 4; q++)
            red_add_v4(po + 4 * q,
                       coef * (tv[4 * q + 0] - ds * v0[4 * q + 0]),
                       coef * (tv[4 * q + 1] - ds * v0[4 * q + 1]),
                       coef * (tv[4 * q + 2] - ds * v0[4 * q + 2]),
                       coef * (tv[4 * q + 3] - ds * v0[4 * q + 3]));
    }

    // message to dst: += coef * F_d(F_s x_s)
    {
        float tv[16];
        float ss = 0.f;
        #pragma unroll
        for (int i = 0; i < 16; i++) ss += v0[i] * in[i];
        ss *= 2.f;
        #pragma unroll
        for (int i = 0; i < 16; i++) tv[i] = in[i] - ss * v0[i];
        float sd = 0.f;
        #pragma unroll
        for (int i = 0; i < 16; i++) sd += v1[i] * tv[i];
        sd *= 2.f;
        float* pq = out + (size_t)d * NDIM;
        #pragma unroll
        for (int q = 0; q < 4; q++)
            red_add_v4(pq + 4 * q,
                       coef * (tv[4 * q + 0] - sd * v1[4 * q + 0]),
                       coef * (tv[4 * q + 1] - sd * v1[4 * q + 1]),
                       coef * (tv[4 * q + 2] - sd * v1[4 * q + 2]),
                       coef * (tv[4 * q + 3] - sd * v1[4 * q + 3]));
    }
}

extern "C" void kernel_launch(void* const* d_in, const int* in_sizes, int n_in,
                              void* d_out, int out_size) {
    const float* x  = (const float*)d_in[0];
    const int*   ei = (const int*)d_in[1];
    const float* W1 = (const float*)d_in[2];
    const float* b1 = (const float*)d_in[3];
    const float* W2 = (const float*)d_in[4];
    const float* b2 = (const float*)d_in[5];
    float* out = (float*)d_out;

    int n  = in_sizes[0] / NDIM;
    int E  = in_sizes[1] / 2;
    int nd = n * NDIM;

    init_kernel<<<(nd + 255) / 256, 256>>>(x, out, n);
    deg_kernel<<<(E + 255) / 256, 256>>>(ei, E, n);
    edge_kernel<<<(E + 127) / 128, 128>>>(x, ei, W1, b1, W2, b2, out, E, n);
    relu_kernel<<<(nd + 255) / 256, 256>>>(out, nd);
}

// round 16
// speedup vs baseline: 1.4649x; 1.4649x over previous
#include <cuda_runtime.h>
#include <cstdint>

#define NDIM 16
#define MAXN 50048

__device__ float g_deg[MAXN];

// ---------- packed f32x2 helpers ----------
__device__ __forceinline__ void ffma2(uint64_t &acc, uint64_t a, uint64_t b) {
    asm("fma.rn.f32x2 %0, %1, %2, %0;" : "+l"(acc) : "l"(a), "l"(b));
}
__device__ __forceinline__ uint64_t pack2(float lo, float hi) {
    uint64_t r; asm("mov.b64 %0, {%1, %2};" : "=l"(r) : "f"(lo), "f"(hi)); return r;
}
__device__ __forceinline__ void unpack2(uint64_t v, float &lo, float &hi) {
    asm("mov.b64 {%0, %1}, %2;" : "=f"(lo), "=f"(hi) : "l"(v));
}
__device__ __forceinline__ void red_add_v4(float* p, float a, float b, float c, float d) {
    asm volatile("red.global.add.v4.f32 [%0], {%1, %2, %3, %4};"
                 :: "l"(p), "f"(a), "f"(b), "f"(c), "f"(d) : "memory");
}

// ---------- small utility kernels ----------
__global__ void init_kernel(const float* __restrict__ x, float* __restrict__ out, int n) {
    int i = blockIdx.x * blockDim.x + threadIdx.x;
    int nd = n * NDIM;
    if (i < nd) out[i] = x[i];
    if (i < n) g_deg[i] = 0.f;
}

__global__ void deg_kernel(const int* __restrict__ ei, int E, int n) {
    int e = blockIdx.x * blockDim.x + threadIdx.x;
    if (e >= E) return;
    int s = ei[e], d = ei[E + e];
    if ((unsigned)s < (unsigned)n) atomicAdd(&g_deg[s], 1.f);
    if ((unsigned)d < (unsigned)n) atomicAdd(&g_deg[d], 1.f);
}

__global__ void relu_kernel(float* __restrict__ out, int nd) {
    int i = blockIdx.x * blockDim.x + threadIdx.x;
    if (i < nd) out[i] = fmaxf(out[i], 0.f);
}

// ---------- main edge kernel: one edge/thread, f32x2 MLP, scalar v-accum, red.v4 ----------
__global__ void __launch_bounds__(128)
edge_kernel(const float* __restrict__ x, const int* __restrict__ ei,
            const float* __restrict__ W1, const float* __restrict__ b1,
            const float* __restrict__ W2, const float* __restrict__ b2,
            float* __restrict__ out, int E, int n)
{
    // sW1[k][j] = W1[j][k]  (transposed: j contiguous -> LDS.128 gives packed (j,j+1) pairs)
    __shared__ __align__(16) float sW1[32 * 64];
    // sW2[i][j] = W2[i][j]
    __shared__ __align__(16) float sW2[16 * 64];
    __shared__ float sb1[64];
    __shared__ float sb2[16];

    for (int idx = threadIdx.x; idx < 64 * 32; idx += blockDim.x) {
        int j = idx >> 5, k = idx & 31;
        sW1[k * 64 + j] = W1[idx];
    }
    for (int idx = threadIdx.x; idx < 16 * 64; idx += blockDim.x) sW2[idx] = W2[idx];
    if (threadIdx.x < 64) sb1[threadIdx.x] = b1[threadIdx.x];
    if (threadIdx.x < 16) sb2[threadIdx.x] = b2[threadIdx.x];
    __syncthreads();

    int e = blockIdx.x * blockDim.x + threadIdx.x;
    if (e >= E) return;
    int s = ei[e];
    int d = ei[E + e];
    if ((unsigned)s >= (unsigned)n || (unsigned)d >= (unsigned)n) return;

    // in[0..15] = x[src], in[16..31] = x[dst]
    float in[32];
    {
        const float4* ps = (const float4*)(x + (size_t)s * NDIM);
        const float4* pd = (const float4*)(x + (size_t)d * NDIM);
        #pragma unroll
        for (int q = 0; q < 4; q++) {
            float4 a = ps[q];
            in[4 * q + 0] = a.x; in[4 * q + 1] = a.y;
            in[4 * q + 2] = a.z; in[4 * q + 3] = a.w;
        }
        #pragma unroll
        for (int q = 0; q < 4; q++) {
            float4 a = pd[q];
            in[16 + 4 * q + 0] = a.x; in[16 + 4 * q + 1] = a.y;
            in[16 + 4 * q + 2] = a.z; in[16 + 4 * q + 3] = a.w;
        }
    }

    // Scalar accumulators for MLP outputs (saves 32 regs vs packed pairs).
    float v0[16], v1[16];
    #pragma unroll
    for (int i = 0; i < 16; i++) { v0[i] = 0.f; v1[i] = 0.f; }

    #pragma unroll 1
    for (int jj = 0; jj < 64; jj += 8) {
        // hp[dir][p] = packed (h_{jj+2p}, h_{jj+2p+1})
        uint64_t hp0[4], hp1[4];
        #pragma unroll
        for (int p = 0; p < 4; p++) {
            uint64_t b = pack2(sb1[jj + 2 * p], sb1[jj + 2 * p + 1]);
            hp0[p] = b; hp1[p] = b;
        }
        #pragma unroll
        for (int k = 0; k < 32; k++) {
            ulonglong2 wa = *(const ulonglong2*)(sW1 + k * 64 + jj);      // pairs (j0,j1),(j2,j3)
            ulonglong2 wb = *(const ulonglong2*)(sW1 + k * 64 + jj + 4);  // pairs (j4,j5),(j6,j7)
            uint64_t A0 = pack2(in[k], in[k]);
            uint64_t A1 = pack2(in[k ^ 16], in[k ^ 16]);
            ffma2(hp0[0], wa.x, A0); ffma2(hp1[0], wa.x, A1);
            ffma2(hp0[1], wa.y, A0); ffma2(hp1[1], wa.y, A1);
            ffma2(hp0[2], wb.x, A0); ffma2(hp1[2], wb.x, A1);
            ffma2(hp0[3], wb.y, A0); ffma2(hp1[3], wb.y, A1);
        }
        // ReLU on packed pairs
        #pragma unroll
        for (int p = 0; p < 4; p++) {
            float l, h;
            unpack2(hp0[p], l, h);
            hp0[p] = pack2(fmaxf(l, 0.f), fmaxf(h, 0.f));
            unpack2(hp1[p], l, h);
            hp1[p] = pack2(fmaxf(l, 0.f), fmaxf(h, 0.f));
        }
        // W2 pass: short packed temps folded into scalar accumulators
        #pragma unroll
        for (int i = 0; i < 16; i++) {
            ulonglong2 wa = *(const ulonglong2*)(sW2 + i * 64 + jj);
            ulonglong2 wb = *(const ulonglong2*)(sW2 + i * 64 + jj + 4);
            uint64_t t0 = 0ull, t1 = 0ull;
            ffma2(t0, wa.x, hp0[0]); ffma2(t0, wa.y, hp0[1]);
            ffma2(t0, wb.x, hp0[2]); ffma2(t0, wb.y, hp0[3]);
            ffma2(t1, wa.x, hp1[0]); ffma2(t1, wa.y, hp1[1]);
            ffma2(t1, wb.x, hp1[2]); ffma2(t1, wb.y, hp1[3]);
            float l, h;
            unpack2(t0, l, h); v0[i] += l + h;
            unpack2(t1, l, h); v1[i] += l + h;
        }
    }

    // add bias, normalize
    float n0 = 0.f, n1 = 0.f;
    #pragma unroll
    for (int i = 0; i < 16; i++) {
        v0[i] += sb2[i]; v1[i] += sb2[i];
        n0 += v0[i] * v0[i];
        n1 += v1[i] * v1[i];
    }
    float inv0 = 1.f / fmaxf(sqrtf(n0), 1e-12f);
    float inv1 = 1.f / fmaxf(sqrtf(n1), 1e-12f);
    #pragma unroll
    for (int i = 0; i < 16; i++) { v0[i] *= inv0; v1[i] *= inv1; }
    // v0 = Householder vec of F_s, v1 = of F_d

    float coef = rsqrtf(fmaxf(g_deg[s], 1e-5f)) * rsqrtf(fmaxf(g_deg[d], 1e-5f));

    // message to src: += coef * F_s(F_d x_d);  F u y = y - 2(u.y)u
    {
        float tv[16];
        float dd = 0.f;
        #pragma unroll
        for (int i = 0; i < 16; i++) dd += v1[i] * in[16 + i];
        dd *= 2.f;
        #pragma unroll
        for (int i = 0; i < 16; i++) tv[i] = in[16 + i] - dd * v1[i];
        float ds = 0.f;
        #pragma unroll
        for (int i = 0; i < 16; i++) ds += v0[i] * tv[i];
        ds *= 2.f;
        float* po = out + (size_t)s * NDIM;
        #pragma unroll
        for (int q = 0; q < 4; q++)
            red_add_v4(po + 4 * q,
                       coef * (tv[4 * q + 0] - ds * v0[4 * q + 0]),
                       coef * (tv[4 * q + 1] - ds * v0[4 * q + 1]),
                       coef * (tv[4 * q + 2] - ds * v0[4 * q + 2]),
                       coef * (tv[4 * q + 3] - ds * v0[4 * q + 3]));
    }

    // message to dst: += coef * F_d(F_s x_s)
    {
        float tv[16];
        float ss = 0.f;
        #pragma unroll
        for (int i = 0; i < 16; i++) ss += v0[i] * in[i];
        ss *= 2.f;
        #pragma unroll
        for (int i = 0; i < 16; i++) tv[i] = in[i] - ss * v0[i];
        float sd = 0.f;
        #pragma unroll
        for (int i = 0; i < 16; i++) sd += v1[i] * tv[i];
        sd *= 2.f;
        float* pq = out + (size_t)d * NDIM;
        #pragma unroll
        for (int q = 0; q < 4; q++)
            red_add_v4(pq + 4 * q,
                       coef * (tv[4 * q + 0] - sd * v1[4 * q + 0]),
                       coef * (tv[4 * q + 1] - sd * v1[4 * q + 1]),
                       coef * (tv[4 * q + 2] - sd * v1[4 * q + 2]),
                       coef * (tv[4 * q + 3] - sd * v1[4 * q + 3]));
    }
}

extern "C" void kernel_launch(void* const* d_in, const int* in_sizes, int n_in,
                              void* d_out, int out_size) {
    const float* x  = (const float*)d_in[0];
    const int*   ei = (const int*)d_in[1];
    const float* W1 = (const float*)d_in[2];
    const float* b1 = (const float*)d_in[3];
    const float* W2 = (const float*)d_in[4];
    const float* b2 = (const float*)d_in[5];
    float* out = (float*)d_out;

    int n  = in_sizes[0] / NDIM;
    int E  = in_sizes[1] / 2;
    int nd = n * NDIM;

    init_kernel<<<(nd + 255) / 256, 256>>>(x, out, n);
    deg_kernel<<<(E + 255) / 256, 256>>>(ei, E, n);
    edge_kernel<<<(E + 127) / 128, 128>>>(x, ei, W1, b1, W2, b2, out, E, n);
    relu_kernel<<<(nd + 255) / 256, 256>>>(out, nd);
}

// round 17
// speedup vs baseline: 1.8507x; 1.2634x over previous
#include <cuda_runtime.h>
#include <cstdint>

#define NDIM 16
#define MAXN 50048

__device__ float g_deg[MAXN];

__constant__ float cW1[64 * 32];   // [j][k] row-major, as provided
__constant__ float cW2[16 * 64];   // [i][j] row-major
__constant__ float cb1[64];
__constant__ float cb2[16];

// ---------- packed f32x2 helpers ----------
__device__ __forceinline__ void ffma2(uint64_t &acc, uint64_t a, uint64_t b) {
    asm("fma.rn.f32x2 %0, %1, %2, %0;" : "+l"(acc) : "l"(a), "l"(b));
}
__device__ __forceinline__ uint64_t pack2(float lo, float hi) {
    uint64_t r; asm("mov.b64 %0, {%1, %2};" : "=l"(r) : "f"(lo), "f"(hi)); return r;
}
__device__ __forceinline__ void unpack2(uint64_t v, float &lo, float &hi) {
    asm("mov.b64 {%0, %1}, %2;" : "=f"(lo), "=f"(hi) : "l"(v));
}
__device__ __forceinline__ void red_add_v4(float* p, float a, float b, float c, float d) {
    asm volatile("red.global.add.v4.f32 [%0], {%1, %2, %3, %4};"
                 :: "l"(p), "f"(a), "f"(b), "f"(c), "f"(d) : "memory");
}

union F4U { float4 f; ulonglong2 u; };

// ---------- small utility kernels ----------
__global__ void init_kernel(const float* __restrict__ x, float* __restrict__ out, int n) {
    int i = blockIdx.x * blockDim.x + threadIdx.x;
    int nd = n * NDIM;
    if (i < nd) out[i] = x[i];
    if (i < n) g_deg[i] = 0.f;
}

__global__ void deg_kernel(const int* __restrict__ ei, int E, int n) {
    int e = blockIdx.x * blockDim.x + threadIdx.x;
    if (e >= E) return;
    int s = ei[e], d = ei[E + e];
    if ((unsigned)s < (unsigned)n) atomicAdd(&g_deg[s], 1.f);
    if ((unsigned)d < (unsigned)n) atomicAdd(&g_deg[d], 1.f);
}

__global__ void relu_kernel(float* __restrict__ out, int nd) {
    int i = blockIdx.x * blockDim.x + threadIdx.x;
    if (i < nd) out[i] = fmaxf(out[i], 0.f);
}

// ---------- main edge kernel: weights in __constant__, f32x2 pairs over k ----------
__global__ void __launch_bounds__(128)
edge_kernel(const float* __restrict__ x, const int* __restrict__ ei,
            float* __restrict__ out, int E, int n)
{
    int e = blockIdx.x * blockDim.x + threadIdx.x;
    if (e >= E) return;
    int s = ei[e];
    int d = ei[E + e];
    if ((unsigned)s >= (unsigned)n || (unsigned)d >= (unsigned)n) return;

    // inP[p] = packed (in[2p], in[2p+1]); p 0..7 = x[src], p 8..15 = x[dst]
    // dir0 input pair p ; dir1 input pair = p ^ 8 (the 16-float halves swap pair-aligned)
    uint64_t inP[16];
    {
        const float4* ps = (const float4*)(x + (size_t)s * NDIM);
        const float4* pd = (const float4*)(x + (size_t)d * NDIM);
        #pragma unroll
        for (int q = 0; q < 4; q++) {
            F4U a; a.f = ps[q];
            inP[2 * q] = a.u.x; inP[2 * q + 1] = a.u.y;
        }
        #pragma unroll
        for (int q = 0; q < 4; q++) {
            F4U a; a.f = pd[q];
            inP[8 + 2 * q] = a.u.x; inP[8 + 2 * q + 1] = a.u.y;
        }
    }

    float v0[16], v1[16];
    #pragma unroll
    for (int i = 0; i < 16; i++) { v0[i] = 0.f; v1[i] = 0.f; }

    #pragma unroll 1
    for (int jj = 0; jj < 64; jj += 8) {
        float h0[8], h1[8];
        #pragma unroll
        for (int j8 = 0; j8 < 8; j8++) {
            int j = jj + j8;
            uint64_t a0 = 0ull, a1 = 0ull;
            #pragma unroll
            for (int q = 0; q < 8; q++) {
                F4U w; w.f = *reinterpret_cast<const float4*>(cW1 + j * 32 + 4 * q);
                // w.u.x = weights for k=4q,4q+1 ; w.u.y = k=4q+2,4q+3
                ffma2(a0, w.u.x, inP[2 * q]);
                ffma2(a0, w.u.y, inP[2 * q + 1]);
                ffma2(a1, w.u.x, inP[(2 * q) ^ 8]);
                ffma2(a1, w.u.y, inP[(2 * q + 1) ^ 8]);
            }
            float b = cb1[j];
            float lo, hi;
            unpack2(a0, lo, hi); h0[j8] = fmaxf(lo + hi + b, 0.f);
            unpack2(a1, lo, hi); h1[j8] = fmaxf(lo + hi + b, 0.f);
        }
        // pack hidden pairs (j, j+1) for the W2 pass
        uint64_t hq0[4], hq1[4];
        #pragma unroll
        for (int p = 0; p < 4; p++) {
            hq0[p] = pack2(h0[2 * p], h0[2 * p + 1]);
            hq1[p] = pack2(h1[2 * p], h1[2 * p + 1]);
        }
        #pragma unroll
        for (int i = 0; i < 16; i++) {
            F4U wA; wA.f = *reinterpret_cast<const float4*>(cW2 + i * 64 + jj);
            F4U wB; wB.f = *reinterpret_cast<const float4*>(cW2 + i * 64 + jj + 4);
            uint64_t t0 = 0ull, t1 = 0ull;
            ffma2(t0, wA.u.x, hq0[0]); ffma2(t0, wA.u.y, hq0[1]);
            ffma2(t0, wB.u.x, hq0[2]); ffma2(t0, wB.u.y, hq0[3]);
            ffma2(t1, wA.u.x, hq1[0]); ffma2(t1, wA.u.y, hq1[1]);
            ffma2(t1, wB.u.x, hq1[2]); ffma2(t1, wB.u.y, hq1[3]);
            float lo, hi;
            unpack2(t0, lo, hi); v0[i] += lo + hi;
            unpack2(t1, lo, hi); v1[i] += lo + hi;
        }
    }

    // add bias, normalize: u = v / max(||v||, 1e-12)
    float n0 = 0.f, n1 = 0.f;
    #pragma unroll
    for (int i = 0; i < 16; i++) {
        v0[i] += cb2[i]; v1[i] += cb2[i];
        n0 += v0[i] * v0[i];
        n1 += v1[i] * v1[i];
    }
    float inv0 = 1.f / fmaxf(sqrtf(n0), 1e-12f);
    float inv1 = 1.f / fmaxf(sqrtf(n1), 1e-12f);
    #pragma unroll
    for (int i = 0; i < 16; i++) { v0[i] *= inv0; v1[i] *= inv1; }
    // v0 = Householder vec of F_s, v1 = of F_d

    // scalar views of the inputs for the message phase
    float xin[32];
    #pragma unroll
    for (int p = 0; p < 16; p++) {
        float lo, hi;
        unpack2(inP[p], lo, hi);
        xin[2 * p] = lo; xin[2 * p + 1] = hi;
    }

    float coef = rsqrtf(fmaxf(g_deg[s], 1e-5f)) * rsqrtf(fmaxf(g_deg[d], 1e-5f));

    // message to src: += coef * F_s(F_d x_d);  F u y = y - 2(u.y)u
    {
        float tv[16];
        float dd = 0.f;
        #pragma unroll
        for (int i = 0; i < 16; i++) dd += v1[i] * xin[16 + i];
        dd *= 2.f;
        #pragma unroll
        for (int i = 0; i < 16; i++) tv[i] = xin[16 + i] - dd * v1[i];
        float ds = 0.f;
        #pragma unroll
        for (int i = 0; i < 16; i++) ds += v0[i] * tv[i];
        ds *= 2.f;
        float* po = out + (size_t)s * NDIM;
        #pragma unroll
        for (int q = 0; q < 4; q++)
            red_add_v4(po + 4 * q,
                       coef * (tv[4 * q + 0] - ds * v0[4 * q + 0]),
                       coef * (tv[4 * q + 1] - ds * v0[4 * q + 1]),
                       coef * (tv[4 * q + 2] - ds * v0[4 * q + 2]),
                       coef * (tv[4 * q + 3] - ds * v0[4 * q + 3]));
    }

    // message to dst: += coef * F_d(F_s x_s)
    {
        float tv[16];
        float ss = 0.f;
        #pragma unroll
        for (int i = 0; i < 16; i++) ss += v0[i] * xin[i];
        ss *= 2.f;
        #pragma unroll
        for (int i = 0; i < 16; i++) tv[i] = xin[i] - ss * v0[i];
        float sd = 0.f;
        #pragma unroll
        for (int i = 0; i < 16; i++) sd += v1[i] * tv[i];
        sd *= 2.f;
        float* pq = out + (size_t)d * NDIM;
        #pragma unroll
        for (int q = 0; q < 4; q++)
            red_add_v4(pq + 4 * q,
                       coef * (tv[4 * q + 0] - sd * v1[4 * q + 0]),
                       coef * (tv[4 * q + 1] - sd * v1[4 * q + 1]),
                       coef * (tv[4 * q + 2] - sd * v1[4 * q + 2]),
                       coef * (tv[4 * q + 3] - sd * v1[4 * q + 3]));
    }
}

extern "C" void kernel_launch(void* const* d_in, const int* in_sizes, int n_in,
                              void* d_out, int out_size) {
    const float* x  = (const float*)d_in[0];
    const int*   ei = (const int*)d_in[1];
    const float* W1 = (const float*)d_in[2];
    const float* b1 = (const float*)d_in[3];
    const float* W2 = (const float*)d_in[4];
    const float* b2 = (const float*)d_in[5];
    float* out = (float*)d_out;

    int n  = in_sizes[0] / NDIM;
    int E  = in_sizes[1] / 2;
    int nd = n * NDIM;

    // D2D async copies into constant memory (graph-capturable, no allocation)
    cudaMemcpyToSymbolAsync(cW1, W1, 64 * 32 * sizeof(float), 0, cudaMemcpyDeviceToDevice);
    cudaMemcpyToSymbolAsync(cW2, W2, 16 * 64 * sizeof(float), 0, cudaMemcpyDeviceToDevice);
    cudaMemcpyToSymbolAsync(cb1, b1, 64 * sizeof(float), 0, cudaMemcpyDeviceToDevice);
    cudaMemcpyToSymbolAsync(cb2, b2, 16 * sizeof(float), 0, cudaMemcpyDeviceToDevice);

    init_kernel<<<(nd + 255) / 256, 256>>>(x, out, n);
    deg_kernel<<<(E + 255) / 256, 256>>>(ei, E, n);
    edge_kernel<<<(E + 127) / 128, 128>>>(x, ei, out, E, n);
    relu_kernel<<<(nd + 255) / 256, 256>>>(out, nd);
}